// round 16
// baseline (speedup 1.0000x reference)
#include <cuda_runtime.h>
#include <cuda_fp16.h>
#include <math.h>

#define TT 256
#define BB 64
#define DD 1024
#define ND (3*DD)        // 3072
#define MTOT (TT*BB)     // 16384

#define RG 128           // phase-2 recurrence CTAs
#define GRID_ALL 148     // one full wave
#define NTILE_N (ND / 128)        // 24
#define NTILE_M (MTOT / 128)      // 128
#define NTILES (NTILE_M * NTILE_N) // 3072

#define NT 512           // threads per CTA

// ---------------- scratch ----------------
__device__ float g_xproj[(size_t)MTOT * ND];
// h ring in fp16 A-fragment layout: [2][64 kkg][512 u32]
__device__ __align__(16) unsigned g_hfrag[2][64 * 512];
__device__ unsigned g_count;
__device__ unsigned g_release;
__device__ unsigned g_cnt16[16 * 32];   // distributed arrival counters (128B apart)

// ---------------- primitives ----------------
__device__ __forceinline__ unsigned h2pack(float a, float b) {
    __half2 p = __floats2half2_rn(a, b);
    return *(unsigned*)&p;
}

__device__ __forceinline__ unsigned ld_acq(const unsigned* p) {
    unsigned v;
    asm volatile("ld.acquire.gpu.global.b32 %0, [%1];" : "=r"(v) : "l"(p) : "memory");
    return v;
}
__device__ __forceinline__ void red_rel_add(unsigned* p, unsigned v) {
    asm volatile("red.release.gpu.global.add.u32 [%0], %1;" :: "l"(p), "r"(v) : "memory");
}
__device__ __forceinline__ unsigned atom_rel_add(unsigned* p, unsigned v) {
    unsigned old;
    asm volatile("atom.release.gpu.global.add.u32 %0, [%1], %2;"
                 : "=r"(old) : "l"(p), "r"(v) : "memory");
    return old;
}
__device__ __forceinline__ void st_rel(unsigned* p, unsigned v) {
    asm volatile("st.release.gpu.global.b32 [%0], %1;" :: "l"(p), "r"(v) : "memory");
}

__device__ __forceinline__ void mma_f16(float c[4], const unsigned a[4], const unsigned b[2]) {
    asm volatile(
        "mma.sync.aligned.m16n8k16.row.col.f32.f16.f16.f32 "
        "{%0,%1,%2,%3}, {%4,%5,%6,%7}, {%8,%9}, {%0,%1,%2,%3};\n"
        : "+f"(c[0]), "+f"(c[1]), "+f"(c[2]), "+f"(c[3])
        : "r"(a[0]), "r"(a[1]), "r"(a[2]), "r"(a[3]),
          "r"(b[0]), "r"(b[1]));
}

__device__ __forceinline__ bool get_done(const void* p, int idx, int flag) {
    if (flag == 1) return ((const unsigned char*)p)[idx] != 0;
    if (flag == 0) return ((const int*)p)[idx] != 0;
    return ((const float*)p)[idx] != 0.0f;
}
__device__ __forceinline__ float sigmoidf_(float x) {
    return 1.0f / (1.0f + __expf(-x));
}

// ---------------- reset ----------------
__global__ void reset_kernel() {
    int t = threadIdx.x;
    if (t == 0) { g_count = 0u; g_release = 0u; }
    if (t < 16) g_cnt16[t * 32] = 0u;
}

// ---------------- geometry ----------------
#define FPC 8            // features per recurrence CTA

// phase-1 fp16 smem (u32 words): Ah 128*20 | Bp 16*132
#define AH_W 20
#define BP_W 132
#define P1_AH 0
#define P1_BP (128 * AH_W)           // 2560

// phase-2 smem (u32 words): ws 12288 | ps[4] 4*64*26 | bh 8
#define WS_U32  12288
#define PS2_S   26
#define PSBUF   (BB * PS2_S)                 // 1664
#define OFF_PS  WS_U32
#define OFF_BH  (WS_U32 + 4 * PSBUF)
#define SMEM_WORDS (OFF_BH + 8)
#define SMEM_BYTES (SMEM_WORDS * 4)          // 75,840 B

__device__ __forceinline__ void grid_barrier(unsigned expected) {
    __syncthreads();
    if (threadIdx.x == 0) {
        unsigned prev = atom_rel_add(&g_count, 1u);
        if (prev + 1u == expected) {
            st_rel(&g_release, expected);
        } else {
            while (ld_acq(&g_release) < expected) { }
        }
    }
    __syncthreads();
}

// ---------------- phase 1: xproj tiles (fp16 m16n8k16) ----------------
// Work done by tid<256; warps 8..15 just join the syncthreads.
__device__ void phase1_xproj(unsigned* smu, const float* __restrict__ ins,
                             const float* __restrict__ Wi,
                             const float* __restrict__ bi, int bid, bool act)
{
    unsigned* Ah = &smu[P1_AH];
    unsigned* Bp = &smu[P1_BP];

    int tid  = threadIdx.x;
    int warp = tid >> 5, lane = tid & 31;
    int wm = warp >> 2, wn = warp & 3;
    int g = lane >> 2, tg = lane & 3;

    int ra = tid >> 3;            // 0..31 (for act threads)
    int ca = (tid & 7) << 2;
    int qb = tid >> 4;            // 0..15
    int cb = (tid & 15) << 3;

    for (int tile = bid; tile < NTILES; tile += GRID_ALL) {
        int mb = tile / NTILE_N, nb = tile % NTILE_N;
        int mBase = mb * 128, nBase = nb * 128;

        float acc[4][4][4];
#pragma unroll
        for (int mt = 0; mt < 4; mt++)
#pragma unroll
            for (int nt = 0; nt < 4; nt++)
#pragma unroll
                for (int i = 0; i < 4; i++) acc[mt][nt][i] = 0.0f;

        float4 av[4], bv[4];
        if (act) {
#pragma unroll
            for (int p = 0; p < 4; p++)
                av[p] = *(const float4*)&ins[(size_t)(mBase + ra + p * 32) * DD + ca];
#pragma unroll
            for (int j = 0; j < 4; j++)
                bv[j] = *(const float4*)&Wi[(size_t)(2 * qb + (j >> 1)) * ND + nBase + cb + (j & 1) * 4];
        }

        for (int kb = 0; kb < DD; kb += 32) {
            if (act) {
#pragma unroll
                for (int p = 0; p < 4; p++) {
                    int w = (ra + p * 32) * AH_W + (ca >> 1);
                    Ah[w]     = h2pack(av[p].x, av[p].y);
                    Ah[w + 1] = h2pack(av[p].z, av[p].w);
                }
                uint4 w0, w1;
                w0.x = h2pack(bv[0].x, bv[2].x); w0.y = h2pack(bv[0].y, bv[2].y);
                w0.z = h2pack(bv[0].z, bv[2].z); w0.w = h2pack(bv[0].w, bv[2].w);
                w1.x = h2pack(bv[1].x, bv[3].x); w1.y = h2pack(bv[1].y, bv[3].y);
                w1.z = h2pack(bv[1].z, bv[3].z); w1.w = h2pack(bv[1].w, bv[3].w);
                *(uint4*)&Bp[qb * BP_W + cb]     = w0;
                *(uint4*)&Bp[qb * BP_W + cb + 4] = w1;
            }
            __syncthreads();

            if (act && kb + 32 < DD) {
#pragma unroll
                for (int p = 0; p < 4; p++)
                    av[p] = *(const float4*)&ins[(size_t)(mBase + ra + p * 32) * DD + kb + 32 + ca];
#pragma unroll
                for (int j = 0; j < 4; j++)
                    bv[j] = *(const float4*)&Wi[(size_t)(kb + 32 + 2 * qb + (j >> 1)) * ND + nBase + cb + (j & 1) * 4];
            }

            if (act) {
#pragma unroll
                for (int kkq = 0; kkq < 2; kkq++) {
                    unsigned a[4][4];
#pragma unroll
                    for (int mt = 0; mt < 4; mt++) {
                        int r0 = wm * 64 + mt * 16;
                        int base0 = (r0 + g) * AH_W + kkq * 8 + tg;
                        int base1 = (r0 + 8 + g) * AH_W + kkq * 8 + tg;
                        a[mt][0] = Ah[base0];
                        a[mt][1] = Ah[base1];
                        a[mt][2] = Ah[base0 + 4];
                        a[mt][3] = Ah[base1 + 4];
                    }
                    unsigned b[4][2];
#pragma unroll
                    for (int nt = 0; nt < 4; nt++) {
                        int c0 = wn * 32 + nt * 8 + g;
                        int q0 = kkq * 8 + tg;
                        b[nt][0] = Bp[q0 * BP_W + c0];
                        b[nt][1] = Bp[(q0 + 4) * BP_W + c0];
                    }
#pragma unroll
                    for (int mt = 0; mt < 4; mt++)
#pragma unroll
                        for (int nt = 0; nt < 4; nt++)
                            mma_f16(acc[mt][nt], a[mt], b[nt]);
                }
            }
            __syncthreads();
        }

        if (act) {
#pragma unroll
            for (int mt = 0; mt < 4; mt++) {
#pragma unroll
                for (int nt = 0; nt < 4; nt++) {
                    int col = nBase + wn * 32 + nt * 8 + 2 * tg;
                    float b0 = bi[col], b1 = bi[col + 1];
                    int r0 = mBase + wm * 64 + mt * 16 + g;
                    float2 v0 = make_float2(acc[mt][nt][0] + b0, acc[mt][nt][1] + b1);
                    float2 v1 = make_float2(acc[mt][nt][2] + b0, acc[mt][nt][3] + b1);
                    *(float2*)&g_xproj[(size_t)r0 * ND + col] = v0;
                    *(float2*)&g_xproj[(size_t)(r0 + 8) * ND + col] = v1;
                }
            }
        }
        __syncthreads();
    }
}

// ---------------- fused persistent kernel ----------------
__global__ __launch_bounds__(NT) void fused_kernel(
    const float* __restrict__ ins, const float* __restrict__ hiddens,
    const void* __restrict__ dones, const float* __restrict__ init_carry,
    const float* __restrict__ Wi, const float* __restrict__ Wh,
    const float* __restrict__ bi, const float* __restrict__ bhn,
    float* __restrict__ out)
{
    extern __shared__ unsigned smu[];
    int bid = blockIdx.x;
    int tid = threadIdx.x;

    int warp = tid >> 5, lane = tid & 31;
    bool act = tid < 256;

    // dones-dtype detection (first 1024 bytes; safe for smallest u8 layout)
    int dflag;
    {
        int lf = 0, li = 0;
        const float* pf = (const float*)dones;
        const int*   pi = (const int*)dones;
        for (int i = lane; i < 256; i += 32) {
            float v = pf[i];
            if (!(v == 0.0f || v == 1.0f)) lf = 1;
            int w = pi[i];
            if (!(w == 0 || w == 1)) li = 1;
        }
        lf = __any_sync(0xffffffffu, lf);
        li = __any_sync(0xffffffffu, li);
        dflag = (!lf) ? 2 : ((!li) ? 0 : 1);
    }

    // recurrence geometry (valid when bid < RG)
    int f0 = bid * FPC;
    int sub = bid & 1;
    int kgown = bid >> 1;

    // per-thread epilogue slot (act threads): one (b, feature-pair)
    int b_s = (tid & 255) >> 2;
    int jp_s = (tid & 3) << 1;
    int idx_s;
    {
        int half = (b_s >> 3) & 1, g_s = b_s & 7, wm_s = b_s >> 4;
        int tg_s = jp_s >> 1;
        idx_s = wm_s * 128 + g_s * 16 + tg_s * 4 + sub * 2 + half;
    }

    // prologue: h_eff[0]; carry own pair in regs; write ring[0] slice
    float he0 = 0.f, he1 = 0.f;
    if (act && bid < RG) {
        int b = b_s, f = f0 + jp_s;
        bool dn = get_done(dones, b, dflag);
        float v0 = dn ? hiddens[(size_t)b * DD + f]     : init_carry[(size_t)b * DD + f];
        float v1 = dn ? hiddens[(size_t)b * DD + f + 1] : init_carry[(size_t)b * DD + f + 1];
        he0 = v0; he1 = v1;
        g_hfrag[0][kgown * 512 + idx_s] = h2pack(v0, v1);
    }

    // ---------------- phase 1 ----------------
    phase1_xproj(smu, ins, Wi, bi, bid, act);

    grid_barrier(GRID_ALL);
    if (bid >= RG) return;

    // ---------------- phase 2 setup ----------------
    unsigned* ws    = smu;                       // b-frags: 64 kg x 3 ntw x 32 lanes x 2 u32
    float*    psall = (float*)&smu[OFF_PS];      // 4 partial buffers, stride PSBUF
    float*    bh_s  = (float*)&smu[OFF_BH];

    int wm = warp & 3;            // m-tile (16 rows)
    int kq = warp >> 2;           // k-quarter (0..3): kkg [kq*16, kq*16+16)
    int g = lane >> 2, tg = lane & 3;

    // one-time: W_h slice (24 cols) as fragment-major fp16 b-frags
    for (int idx = tid; idx < 64 * 3 * 32; idx += NT) {
        int l = idx & 31;
        int ntw = (idx >> 5) % 3;
        int kg = idx / 96;
        int c = ntw * 8 + (l >> 2);           // 0..23
        int gate = c >> 3, j = c & 7;
        size_t colg = (size_t)gate * DD + f0 + j;
        int k0 = kg * 16 + 2 * (l & 3);
        float w0 = Wh[(size_t)k0 * ND + colg];
        float w1 = Wh[(size_t)(k0 + 1) * ND + colg];
        float w2 = Wh[(size_t)(k0 + 8) * ND + colg];
        float w3 = Wh[(size_t)(k0 + 9) * ND + colg];
        ws[(size_t)idx * 2 + 0] = h2pack(w0, w1);
        ws[(size_t)idx * 2 + 1] = h2pack(w2, w3);
    }
    if (tid < 8) bh_s[tid] = bhn[f0 + tid];
    __syncthreads();

    int abase = wm * 32 + lane;     // uint4 index within a kkg block
    int kqbase = kq * 16;
    int mycnt = (bid & 15) * 32;
    float* mydst = psall + kq * PSBUF;

    for (int t = 0; t < TT; t++) {
        const uint4* rbuf = (const uint4*)&g_hfrag[t & 1][0];
        unsigned* wr = &g_hfrag[(t + 1) & 1][kgown * 512];

        float acc[3][4];
#pragma unroll
        for (int n = 0; n < 3; n++)
#pragma unroll
            for (int i = 0; i < 4; i++) acc[n][i] = 0.0f;

        // epilogue operand prefetch FIRST (independent of h ring; hides under wait)
        float2 xrv, xzv, xnv, hvv;
        int dnp = 0;
        if (act) {
            int b = b_s;
            size_t base = ((size_t)t * BB + b) * ND + f0 + jp_s;
            xrv = *(const float2*)&g_xproj[base];
            xzv = *(const float2*)&g_xproj[base + DD];
            xnv = *(const float2*)&g_xproj[base + 2 * DD];
            if (t < TT - 1) {
                dnp = get_done(dones, (t + 1) * BB + b, dflag) ? 1 : 0;
                hvv = *(const float2*)&hiddens[((size_t)(t + 1) * BB + b) * DD + f0 + jp_s];
            } else { hvv = make_float2(0.f, 0.f); }
        }

        // wait: ring[t&1] complete (all CTAs arrived for step t)
        if (t > 0) {
            if (tid < 16) {
                unsigned need = 8u * (unsigned)t;
                while (ld_acq(&g_cnt16[tid * 32]) < need) { }
            }
            __syncthreads();
        }

        // load all 16 h-fragments for this k-quarter (MLP=16)
        uint4 bufa[16];
#pragma unroll
        for (int u = 0; u < 16; u++)
            bufa[u] = __ldcg(&rbuf[(kqbase + u) * 128 + abase]);

#pragma unroll
        for (int u = 0; u < 16; u++) {
            int kkg = kqbase + u;
            uint4 a4 = bufa[u];
#pragma unroll
            for (int ntw = 0; ntw < 3; ntw++) {
                uint2 b2 = *(const uint2*)&ws[(size_t)((kkg * 3 + ntw) * 32 + lane) * 2];
                mma_f16(acc[ntw], (const unsigned*)&a4, (const unsigned*)&b2);
            }
        }

        // partial-sum stores into this k-quarter's buffer
        {
            int r0 = wm * 16 + g;
#pragma unroll
            for (int ntw = 0; ntw < 3; ntw++) {
                int c0 = ntw * 8 + 2 * tg;
                mydst[r0 * PS2_S + c0]           = acc[ntw][0];
                mydst[r0 * PS2_S + c0 + 1]       = acc[ntw][1];
                mydst[(r0 + 8) * PS2_S + c0]     = acc[ntw][2];
                mydst[(r0 + 8) * PS2_S + c0 + 1] = acc[ntw][3];
            }
        }
        __syncthreads();

        // gates (one feature-pair per act thread)
        float h0 = 0.f, h1 = 0.f;
        if (act) {
            int b = b_s, j = jp_s;
            int rb0 = b * PS2_S;
            float pr0 = psall[rb0 + j]          + psall[PSBUF + rb0 + j]
                      + psall[2*PSBUF + rb0 + j]      + psall[3*PSBUF + rb0 + j];
            float pr1 = psall[rb0 + j + 1]      + psall[PSBUF + rb0 + j + 1]
                      + psall[2*PSBUF + rb0 + j + 1]  + psall[3*PSBUF + rb0 + j + 1];
            float pz0 = psall[rb0 + 8 + j]      + psall[PSBUF + rb0 + 8 + j]
                      + psall[2*PSBUF + rb0 + 8 + j]  + psall[3*PSBUF + rb0 + 8 + j];
            float pz1 = psall[rb0 + 8 + j + 1]  + psall[PSBUF + rb0 + 8 + j + 1]
                      + psall[2*PSBUF + rb0 + 8 + j + 1] + psall[3*PSBUF + rb0 + 8 + j + 1];
            float pn0 = psall[rb0 + 16 + j]     + psall[PSBUF + rb0 + 16 + j]
                      + psall[2*PSBUF + rb0 + 16 + j] + psall[3*PSBUF + rb0 + 16 + j];
            float pn1 = psall[rb0 + 16 + j + 1] + psall[PSBUF + rb0 + 16 + j + 1]
                      + psall[2*PSBUF + rb0 + 16 + j + 1] + psall[3*PSBUF + rb0 + 16 + j + 1];

            float r0 = sigmoidf_(xrv.x + pr0);
            float r1 = sigmoidf_(xrv.y + pr1);
            float z0 = sigmoidf_(xzv.x + pz0);
            float z1 = sigmoidf_(xzv.y + pz1);
            float n0 = tanhf(xnv.x + r0 * (pn0 + bh_s[j]));
            float n1 = tanhf(xnv.y + r1 * (pn1 + bh_s[j + 1]));
            h0 = (1.0f - z0) * n0 + z0 * he0;
            h1 = (1.0f - z1) * n1 + z1 * he1;

            if (t < TT - 1) {
                float nv0 = dnp ? hvv.x : h0;
                float nv1 = dnp ? hvv.y : h1;
                wr[idx_s] = h2pack(nv0, nv1);
                he0 = nv0; he1 = nv1;
            }
        }
        __syncthreads();

        // arrive (h ring for t+1 is published) — then do DRAM output stores
        if (t < TT - 1 && tid == 0) red_rel_add(&g_cnt16[mycnt], 1u);

        if (act) {
            int b = b_s, f = f0 + jp_s;
            *(float2*)&out[BB * DD + ((size_t)t * BB + b) * DD + f] = make_float2(h0, h1);  // ys
            if (t == TT - 1)
                *(float2*)&out[(size_t)b * DD + f] = make_float2(h0, h1);                    // final_carry
        }
    }
}

// ---------------- launch ----------------
extern "C" void kernel_launch(void* const* d_in, const int* in_sizes, int n_in,
                              void* d_out, int out_size) {
    const float* ins        = (const float*)d_in[0];
    const float* hiddens    = (const float*)d_in[1];
    const void*  dones      = (const void*)d_in[2];
    const float* init_carry = (const float*)d_in[3];
    const float* Wi         = (const float*)d_in[4];
    const float* Wh         = (const float*)d_in[5];
    const float* bi         = (const float*)d_in[6];
    const float* bhn        = (const float*)d_in[7];
    float* out = (float*)d_out;

    static int smem_set = 0;
    if (!smem_set) {
        cudaFuncSetAttribute(fused_kernel,
            cudaFuncAttributeMaxDynamicSharedMemorySize, SMEM_BYTES);
        smem_set = 1;
    }

    reset_kernel<<<1, 32>>>();
    fused_kernel<<<GRID_ALL, NT, SMEM_BYTES>>>(
        ins, hiddens, dones, init_carry, Wi, Wh, bi, bhn, out);
}